// round 3
// baseline (speedup 1.0000x reference)
#include <cuda_runtime.h>
#include <math.h>

#define BB 16384
#define NN 20
#define DD 128
#define HH 4
#define SCALE 0.1020620726159658f /* 1/sqrt(96) */

typedef unsigned long long u64;

#define PK2(o, lo, hi) \
    asm("mov.b64 %0, {%1, %2};" : "=l"(o) : "r"(__float_as_uint(lo)), "r"(__float_as_uint(hi)))
#define FMA2A(d, a, b) \
    asm("fma.rn.f32x2 %0, %1, %2, %0;" : "+l"(d) : "l"(a), "l"(b))
#define UPK2(lo, hi, v) do { unsigned int _ul, _uh; \
    asm("mov.b64 {%0, %1}, %2;" : "=r"(_ul), "=r"(_uh) : "l"(v)); \
    lo = __uint_as_float(_ul); hi = __uint_as_float(_uh); } while (0)

// ---------------- device scratch ----------------
__device__ float g_qt[(size_t)BB * 1536];   // q-tilde [b][h*384+j]
__device__ float g_c [(size_t)BB * 1536];   // context [b][h*384+j]
__device__ float g_ao[(size_t)BB * 384];    // attn out pre-fc
__device__ float g_ln[(size_t)BB * 384];    // post-LN rows
__device__ float g_WqT[256 * 384];
__device__ float g_WvT[4 * 384 * 96];
__device__ float g_fcT[384 * 384];
__device__ float g_m1T[512 * 128];
__device__ float g_m2T[128 * 128];

// ---------------- weight transposes ----------------
__global__ void k_prep(const float* __restrict__ Wq, const float* __restrict__ Wv,
                       const float* __restrict__ fc_w, const float* __restrict__ m1_w,
                       const float* __restrict__ m2_w) {
    int i = blockIdx.x * 256 + threadIdx.x;
    if (i < 98304) { int m = i / 384, c = i % 384;
        g_WqT[i] = Wq[c * 384 + (m < 128 ? m : m + 128)]; return; }
    i -= 98304;
    if (i < 147456) { int h = i / 36864, r = i % 36864, j = r / 96, d = r % 96;
        g_WvT[i] = Wv[(h * 96 + d) * 384 + j]; return; }
    i -= 147456;
    if (i < 147456) { int k = i / 384, c = i % 384;
        g_fcT[i] = fc_w[c * 384 + k]; return; }
    i -= 147456;
    if (i < 65536) { int k = i / 128, r = i % 128;
        g_m1T[i] = m1_w[r * 512 + k]; return; }
    i -= 65536;
    if (i < 16384) { int k = i / 128, r = i % 128;
        g_m2T[i] = m2_w[r * 128 + k]; return; }
}

// inner step: P row-pairs x 3 cols. sa2 = col-major A pairs (u64), sbf = scalar B.
// A load is warp-broadcast (same addr for all lanes); B loads coalesced.
#define INNER3(ACC, SA2, SPAIRS, SBF, P)                                   \
    _Pragma("unroll 8")                                                    \
    for (int kk = 0; kk < 32; ++kk) {                                      \
        float bv0 = SBF[kk * 96 + ct];                                     \
        float bv1 = SBF[kk * 96 + ct + 32];                                \
        float bv2 = SBF[kk * 96 + ct + 64];                                \
        u64 bp0, bp1, bp2;                                                 \
        PK2(bp0, bv0, bv0); PK2(bp1, bv1, bv1); PK2(bp2, bv2, bv2);        \
        _Pragma("unroll")                                                  \
        for (int p = 0; p < P; ++p) {                                      \
            u64 ap = SA2[kk * SPAIRS + rt * P + p];                        \
            FMA2A(ACC[p][0], ap, bp0);                                     \
            FMA2A(ACC[p][1], ap, bp1);                                     \
            FMA2A(ACC[p][2], ap, bp2);                                     \
        }                                                                  \
    }

// ---------------- q projection + q-tilde: block = (64-batch tile, head) ----------------
__global__ void __launch_bounds__(256) k_qproj(const float* __restrict__ src,
                                               const float* __restrict__ src_ts,
                                               const float* __restrict__ freq,
                                               const float* __restrict__ phase,
                                               const float* __restrict__ Wk) {
    __shared__ __align__(16) float sbf[32 * 96];   // B tile scalar
    __shared__ __align__(16) float saf[32 * 66];   // A col-major, stride 66
    __shared__ __align__(16) float qs[64 * 96];    // q head slice
    __shared__ float sts[64];
    const int tid = threadIdx.x;
    const int ct = tid & 31, rt = tid >> 5;
    const int bt = blockIdx.x >> 2;
    const int h  = blockIdx.x & 3;
    const int b0 = bt * 64;
    const u64* sa2 = (const u64*)saf;

    if (tid < 64) sts[tid] = src_ts[b0 + tid];

    // phase 1: qs(64x96) = A(64x256) @ WqT[:, h*96:+96]
    u64 acc[4][3] = {};
    for (int kt = 0; kt < 256; kt += 32) {
        __syncthreads();
        for (int idx = tid; idx < 2048; idx += 256) {
            int row = idx >> 5, kk = idx & 31;
            int m = kt + kk;
            float v;
            if (m < 128) v = src[(size_t)(b0 + row) * 128 + m];
            else { int d = m - 128; v = cosf(sts[row] * freq[d] + phase[d]); }
            saf[kk * 66 + row] = v;
        }
        for (int idx = tid; idx < 3072; idx += 256) {
            int kk = idx / 96, c = idx - kk * 96;
            sbf[idx] = g_WqT[(kt + kk) * 384 + h * 96 + c];
        }
        __syncthreads();
        INNER3(acc, sa2, 33, sbf, 4)
    }
    __syncthreads();
    #pragma unroll
    for (int p = 0; p < 4; ++p)
        #pragma unroll
        for (int cc = 0; cc < 3; ++cc) {
            float lo, hi; UPK2(lo, hi, acc[p][cc]);
            qs[(rt * 8 + 2 * p) * 96 + ct + 32 * cc] = lo;
            qs[(rt * 8 + 2 * p + 1) * 96 + ct + 32 * cc] = hi;
        }

    // phase 2: qt(64x384) = qs(64x96) @ Wk_h(96x384)
    for (int pass = 0; pass < 4; ++pass) {
        const int c0 = pass * 96;
        u64 a2[4][3] = {};
        for (int kt = 0; kt < 96; kt += 32) {
            __syncthreads();
            for (int idx = tid; idx < 2048; idx += 256) {
                int row = idx >> 5, kk = idx & 31;
                saf[kk * 66 + row] = qs[row * 96 + kt + kk];
            }
            for (int idx = tid; idx < 3072; idx += 256) {
                int kk = idx / 96, c = idx - kk * 96;
                sbf[idx] = Wk[(h * 96 + kt + kk) * 384 + c0 + c];
            }
            __syncthreads();
            INNER3(a2, sa2, 33, sbf, 4)
        }
        #pragma unroll
        for (int p = 0; p < 4; ++p)
            #pragma unroll
            for (int cc = 0; cc < 3; ++cc) {
                float lo, hi; UPK2(lo, hi, a2[p][cc]);
                g_qt[(size_t)(b0 + rt * 8 + 2 * p) * 1536 + h * 384 + c0 + ct + 32 * cc] = lo;
                g_qt[(size_t)(b0 + rt * 8 + 2 * p + 1) * 1536 + h * 384 + c0 + ct + 32 * cc] = hi;
            }
    }
}

// ---------------- attention core: one block per batch element ----------------
__global__ void __launch_bounds__(256) k_attn(const float* __restrict__ seq,
                                              const float* __restrict__ seq_e,
                                              const float* __restrict__ seq_ts,
                                              const unsigned int* __restrict__ mask,
                                              const float* __restrict__ freq,
                                              const float* __restrict__ phase,
                                              float* __restrict__ attn_out) {
    __shared__ float kin[NN * 384];
    __shared__ float qts[1536];
    __shared__ float sc[HH][NN];
    __shared__ float pp[HH][NN];
    const int b = blockIdx.x;
    const int tid = threadIdx.x;
    const int w = tid >> 5, lane = tid & 31;

    const float4* seq4   = (const float4*)seq;
    const float4* seq_e4 = (const float4*)seq_e;
    for (int idx = tid; idx < NN * 32; idx += 256) {
        int n = idx >> 5, q = idx & 31;
        float4 a = seq4  [((size_t)b * NN + n) * 32 + q];
        float4 e = seq_e4[((size_t)b * NN + n) * 32 + q];
        *(float4*)&kin[n * 384 + q * 4]       = a;
        *(float4*)&kin[n * 384 + 128 + q * 4] = e;
    }
    for (int idx = tid; idx < NN * 128; idx += 256) {
        int n = idx >> 7, d = idx & 127;
        kin[n * 384 + 256 + d] = cosf(seq_ts[b * NN + n] * freq[d] + phase[d]);
    }
    const float4* qt4 = (const float4*)(g_qt + (size_t)b * 1536);
    for (int idx = tid; idx < 384; idx += 256)
        *(float4*)&qts[idx * 4] = qt4[idx];
    __syncthreads();

    for (int p = w; p < HH * NN; p += 8) {
        int h = p / NN, n = p - h * NN;
        float partial = 0.f;
        #pragma unroll
        for (int t = 0; t < 12; ++t)
            partial = fmaf(qts[h * 384 + lane + 32 * t], kin[n * 384 + lane + 32 * t], partial);
        #pragma unroll
        for (int off = 16; off; off >>= 1)
            partial += __shfl_xor_sync(0xffffffffu, partial, off);
        if (lane == 0) {
            float s = partial * SCALE;
            if (mask[b * NN + n] != 0u) s = -1.0e10f;
            sc[h][n] = s;
        }
    }
    __syncthreads();

    if (w < HH) {
        float v = (lane < NN) ? sc[w][lane] : -3.0e38f;
        float mx = v;
        #pragma unroll
        for (int off = 16; off; off >>= 1)
            mx = fmaxf(mx, __shfl_xor_sync(0xffffffffu, mx, off));
        float e = (lane < NN) ? expf(v - mx) : 0.f;
        float s = e;
        #pragma unroll
        for (int off = 16; off; off >>= 1)
            s += __shfl_xor_sync(0xffffffffu, s, off);
        float prob = e / s;
        if (lane < NN) {
            pp[w][lane] = prob;
            attn_out[((size_t)w * BB + b) * NN + lane] = prob;
        }
    }
    __syncthreads();

    for (int idx = tid; idx < 1536; idx += 256) {
        int h = idx / 384, j = idx - h * 384;
        float s = 0.f;
        #pragma unroll
        for (int n = 0; n < NN; ++n)
            s = fmaf(pp[h][n], kin[n * 384 + j], s);
        g_c[(size_t)b * 1536 + idx] = s;
    }
}

// ---------------- Wv apply: block = (64-batch tile, head), K=384 ----------------
__global__ void __launch_bounds__(256) k_vout() {
    __shared__ __align__(16) float sbf[32 * 96];
    __shared__ __align__(16) float saf[32 * 66];
    const int tid = threadIdx.x;
    const int ct = tid & 31, rt = tid >> 5;
    const int bt = blockIdx.x >> 2;
    const int h  = blockIdx.x & 3;
    const int b0 = bt * 64;
    const u64* sa2 = (const u64*)saf;

    u64 acc[4][3] = {};
    for (int kt = 0; kt < 384; kt += 32) {
        __syncthreads();
        for (int idx = tid; idx < 2048; idx += 256) {
            int row = idx >> 5, kk = idx & 31;
            saf[kk * 66 + row] = g_c[(size_t)(b0 + row) * 1536 + h * 384 + kt + kk];
        }
        for (int idx = tid; idx < 3072; idx += 256) {
            int kk = idx / 96, c = idx - kk * 96;
            sbf[idx] = g_WvT[h * 36864 + (kt + kk) * 96 + c];
        }
        __syncthreads();
        INNER3(acc, sa2, 33, sbf, 4)
    }
    #pragma unroll
    for (int p = 0; p < 4; ++p)
        #pragma unroll
        for (int cc = 0; cc < 3; ++cc) {
            float lo, hi; UPK2(lo, hi, acc[p][cc]);
            g_ao[(size_t)(b0 + rt * 8 + 2 * p) * 384 + h * 96 + ct + 32 * cc] = lo;
            g_ao[(size_t)(b0 + rt * 8 + 2 * p + 1) * 384 + h * 96 + ct + 32 * cc] = hi;
        }
}

// ---------------- fc + bias + residual + LayerNorm: 32 rows/block ----------------
// dyn smem: pre[32*384] | sbf[32*96] | saf[32*34] | sts[32]
__global__ void __launch_bounds__(256) k_fcln(const float* __restrict__ src,
                                              const float* __restrict__ src_ts,
                                              const float* __restrict__ freq,
                                              const float* __restrict__ phase,
                                              const float* __restrict__ fc_b,
                                              const float* __restrict__ ln_g,
                                              const float* __restrict__ ln_b) {
    extern __shared__ __align__(16) float dynf[];
    float* pre = dynf;                // 12288
    float* sbf = pre + 12288;         // 3072
    float* saf = sbf + 3072;          // 1088 (32 kk x stride 34)
    float* sts = saf + 1088;          // 32
    const int tid = threadIdx.x;
    const int ct = tid & 31, rt = tid >> 5;
    const int b0 = blockIdx.x * 32;
    const u64* sa2 = (const u64*)saf;

    if (tid < 32) sts[tid] = src_ts[b0 + tid];

    for (int cp = 0; cp < 4; ++cp) {
        const int c0 = cp * 96;
        u64 acc[2][3] = {};
        for (int kt = 0; kt < 384; kt += 32) {
            __syncthreads();
            for (int idx = tid; idx < 1024; idx += 256) {
                int row = idx >> 5, kk = idx & 31;
                saf[kk * 34 + row] = g_ao[(size_t)(b0 + row) * 384 + kt + kk];
            }
            for (int idx = tid; idx < 3072; idx += 256) {
                int kk = idx / 96, c = idx - kk * 96;
                sbf[idx] = g_fcT[(kt + kk) * 384 + c0 + c];
            }
            __syncthreads();
            INNER3(acc, sa2, 17, sbf, 2)
        }
        #pragma unroll
        for (int p = 0; p < 2; ++p)
            #pragma unroll
            for (int cc = 0; cc < 3; ++cc) {
                float lo, hi; UPK2(lo, hi, acc[p][cc]);
                const int col = c0 + ct + 32 * cc;
                const int r0 = rt * 4 + 2 * p, r1 = r0 + 1;
                float add0 = fc_b[col], add1 = add0;
                if (col < 128) {
                    add0 += src[(size_t)(b0 + r0) * 128 + col];
                    add1 += src[(size_t)(b0 + r1) * 128 + col];
                } else if (col >= 256) {
                    int d = col - 256;
                    add0 += cosf(sts[r0] * freq[d] + phase[d]);
                    add1 += cosf(sts[r1] * freq[d] + phase[d]);
                }
                pre[r0 * 384 + col] = lo + add0;
                pre[r1 * 384 + col] = hi + add1;
            }
    }
    __syncthreads();

    // LayerNorm: warp rt handles rows 4rt..4rt+3
    for (int rr = 0; rr < 4; ++rr) {
        int row = rt * 4 + rr;
        float s1 = 0.f, s2 = 0.f;
        #pragma unroll
        for (int t = 0; t < 12; ++t) {
            float v = pre[row * 384 + ct + 32 * t];
            s1 += v; s2 = fmaf(v, v, s2);
        }
        #pragma unroll
        for (int off = 16; off; off >>= 1) {
            s1 += __shfl_xor_sync(0xffffffffu, s1, off);
            s2 += __shfl_xor_sync(0xffffffffu, s2, off);
        }
        float mu = s1 * (1.f / 384.f);
        float var = s2 * (1.f / 384.f) - mu * mu;
        float inv = rsqrtf(var + 1e-5f);
        #pragma unroll
        for (int t = 0; t < 12; ++t) {
            int j = ct + 32 * t;
            float v = pre[row * 384 + j];
            g_ln[(size_t)(b0 + row) * 384 + j] = (v - mu) * inv * ln_g[j] + ln_b[j];
        }
    }
}

// ---------------- MLP: 64 rows/block, col-major A operands ----------------
// dyn smem: xs[512*66] | hs[128*66] | sbf[32*128]
__global__ void __launch_bounds__(256) k_mlp(const float* __restrict__ src,
                                             const float* __restrict__ m1_b,
                                             const float* __restrict__ m2_b,
                                             float* __restrict__ y) {
    extern __shared__ __align__(16) float dynf[];
    float* xsf = dynf;                 // 512 x 66 col-major
    float* hsf = xsf + 512 * 66;       // 128 x 66 col-major
    float* sbf = hsf + 128 * 66;       // 32 x 128
    const int tid = threadIdx.x;
    const int ct = tid & 31, rt = tid >> 5;
    const int b0 = blockIdx.x * 64;
    const u64* xs2 = (const u64*)xsf;
    const u64* hs2 = (const u64*)hsf;

    // build x = [ln | src] col-major
    for (int idx = tid; idx < 64 * 384; idx += 256) {
        int r = idx / 384, c = idx - r * 384;
        xsf[c * 66 + r] = g_ln[(size_t)(b0 + r) * 384 + c];
    }
    for (int idx = tid; idx < 64 * 128; idx += 256) {
        int r = idx >> 7, d = idx & 127;
        xsf[(384 + d) * 66 + r] = src[(size_t)(b0 + r) * 128 + d];
    }

    float mb1[4], mb2[4];
    #pragma unroll
    for (int cc = 0; cc < 4; ++cc) {
        mb1[cc] = m1_b[ct + 32 * cc];
        mb2[cc] = m2_b[ct + 32 * cc];
    }

    // GEMM1: h(64x128) = relu(x(64x512) @ m1T + b)
    u64 acc[4][4] = {};
    for (int kt = 0; kt < 512; kt += 32) {
        __syncthreads();
        for (int idx = tid; idx < 4096; idx += 256) {
            int kk = idx >> 7, c = idx & 127;
            sbf[idx] = g_m1T[(kt + kk) * 128 + c];
        }
        __syncthreads();
        #pragma unroll 8
        for (int kk = 0; kk < 32; ++kk) {
            u64 bp[4];
            #pragma unroll
            for (int cc = 0; cc < 4; ++cc) {
                float bv = sbf[kk * 128 + ct + 32 * cc];
                PK2(bp[cc], bv, bv);
            }
            #pragma unroll
            for (int p = 0; p < 4; ++p) {
                u64 ap = xs2[(kt + kk) * 33 + rt * 4 + p];
                #pragma unroll
                for (int cc = 0; cc < 4; ++cc) FMA2A(acc[p][cc], ap, bp[cc]);
            }
        }
    }
    __syncthreads();
    #pragma unroll
    for (int p = 0; p < 4; ++p)
        #pragma unroll
        for (int cc = 0; cc < 4; ++cc) {
            float lo, hi; UPK2(lo, hi, acc[p][cc]);
            int col = ct + 32 * cc;
            hsf[col * 66 + rt * 8 + 2 * p]     = fmaxf(lo + mb1[cc], 0.f);
            hsf[col * 66 + rt * 8 + 2 * p + 1] = fmaxf(hi + mb1[cc], 0.f);
        }

    // GEMM2: y = h(64x128) @ m2T + b
    u64 a2[4][4] = {};
    for (int kt = 0; kt < 128; kt += 32) {
        __syncthreads();
        for (int idx = tid; idx < 4096; idx += 256) {
            int kk = idx >> 7, c = idx & 127;
            sbf[idx] = g_m2T[(kt + kk) * 128 + c];
        }
        __syncthreads();
        #pragma unroll 8
        for (int kk = 0; kk < 32; ++kk) {
            u64 bp[4];
            #pragma unroll
            for (int cc = 0; cc < 4; ++cc) {
                float bv = sbf[kk * 128 + ct + 32 * cc];
                PK2(bp[cc], bv, bv);
            }
            #pragma unroll
            for (int p = 0; p < 4; ++p) {
                u64 ap = hs2[(kt + kk) * 33 + rt * 4 + p];
                #pragma unroll
                for (int cc = 0; cc < 4; ++cc) FMA2A(a2[p][cc], ap, bp[cc]);
            }
        }
    }
    #pragma unroll
    for (int p = 0; p < 4; ++p)
        #pragma unroll
        for (int cc = 0; cc < 4; ++cc) {
            float lo, hi; UPK2(lo, hi, a2[p][cc]);
            int col = ct + 32 * cc;
            y[(size_t)(b0 + rt * 8 + 2 * p) * 128 + col]     = lo + mb2[cc];
            y[(size_t)(b0 + rt * 8 + 2 * p + 1) * 128 + col] = hi + mb2[cc];
        }
}

// ---------------- launch ----------------
extern "C" void kernel_launch(void* const* d_in, const int* in_sizes, int n_in,
                              void* d_out, int out_size) {
    const float* src    = (const float*)d_in[0];
    const float* seq    = (const float*)d_in[1];
    const float* seq_e  = (const float*)d_in[2];
    const float* src_ts = (const float*)d_in[3];
    const float* seq_ts = (const float*)d_in[4];
    const unsigned int* mask = (const unsigned int*)d_in[5];
    const float* freq   = (const float*)d_in[6];
    const float* phase  = (const float*)d_in[7];
    const float* Wq     = (const float*)d_in[8];
    const float* Wk     = (const float*)d_in[9];
    const float* Wv     = (const float*)d_in[10];
    const float* fc_w   = (const float*)d_in[11];
    const float* fc_b   = (const float*)d_in[12];
    const float* ln_g   = (const float*)d_in[13];
    const float* ln_b   = (const float*)d_in[14];
    const float* m1_w   = (const float*)d_in[15];
    const float* m1_b   = (const float*)d_in[16];
    const float* m2_w   = (const float*)d_in[17];
    const float* m2_b   = (const float*)d_in[18];

    float* y_out = (float*)d_out;
    float* attn_out = y_out + (size_t)BB * DD;

    const int fcln_smem = (12288 + 3072 + 1088 + 32) * 4;            // 65920
    const int mlp_smem  = (512 * 66 + 128 * 66 + 32 * 128) * 4;      // 185344
    cudaFuncSetAttribute(k_fcln, cudaFuncAttributeMaxDynamicSharedMemorySize, fcln_smem);
    cudaFuncSetAttribute(k_mlp,  cudaFuncAttributeMaxDynamicSharedMemorySize, mlp_smem);

    k_prep  <<<1856, 256>>>(Wq, Wv, fc_w, m1_w, m2_w);
    k_qproj <<<1024, 256>>>(src, src_ts, freq, phase, Wk);
    k_attn  <<<BB, 256>>>(seq, seq_e, seq_ts, mask, freq, phase, attn_out);
    k_vout  <<<1024, 256>>>();
    k_fcln  <<<512, 256, fcln_smem>>>(src, src_ts, freq, phase, fc_b, ln_g, ln_b);
    k_mlp   <<<256, 256, mlp_smem>>>(src, m1_b, m2_b, y_out);
}

// round 4
// speedup vs baseline: 1.2850x; 1.2850x over previous
#include <cuda_runtime.h>
#include <math.h>

#define BB 16384
#define NN 20
#define DD 128
#define HH 4
#define SCALE 0.1020620726159658f /* 1/sqrt(96) */

typedef unsigned long long u64;

#define PK2(o, lo, hi) \
    asm("mov.b64 %0, {%1, %2};" : "=l"(o) : "r"(__float_as_uint(lo)), "r"(__float_as_uint(hi)))
#define FMA2A(d, a, b) \
    asm("fma.rn.f32x2 %0, %1, %2, %0;" : "+l"(d) : "l"(a), "l"(b))
#define UPK2(lo, hi, v) do { unsigned int _ul, _uh; \
    asm("mov.b64 {%0, %1}, %2;" : "=r"(_ul), "=r"(_uh) : "l"(v)); \
    lo = __uint_as_float(_ul); hi = __uint_as_float(_uh); } while (0)

// ---------------- device scratch ----------------
__device__ float g_qt[(size_t)BB * 1536];   // q-tilde [b][h*384+j]
__device__ float g_c [(size_t)BB * 1536];   // context [b][h*384+j]
__device__ float g_ao[(size_t)BB * 384];    // attn out pre-fc
__device__ float g_pre[(size_t)BB * 384];   // fc + bias + residual (pre-LN)
__device__ float g_WkT[4 * 384 * 96];       // [h][col j][k]

// ---------------- prep: only Wk needs transposing now ----------------
__global__ void k_prep(const float* __restrict__ Wk) {
    int i = blockIdx.x * 256 + threadIdx.x;
    if (i < 147456) {
        int h = i / 36864, rem = i % 36864, col = rem / 96, k = rem % 96;
        g_WkT[i] = Wk[(h * 96 + k) * 384 + col];
    }
}

// ---------- GEMM tile engine: B transposed [col][kk] stride 36, A pairs col-major ----------
template<int NPAIR, int NCOL, int SP>
__device__ __forceinline__ void gemm_tile(u64* acc, const float* saf, const float* sbt,
                                          int ct, int rt) {
    const u64* sa2 = (const u64*)saf;
    #pragma unroll
    for (int k4 = 0; k4 < 8; ++k4) {
        float bqa[NCOL][4];
        #pragma unroll
        for (int c = 0; c < NCOL; ++c)
            *(float4*)bqa[c] = *(const float4*)&sbt[(ct + 32 * c) * 36 + k4 * 4];
        #pragma unroll
        for (int kq = 0; kq < 4; ++kq) {
            const int kk = k4 * 4 + kq;
            u64 bp[NCOL];
            #pragma unroll
            for (int c = 0; c < NCOL; ++c) PK2(bp[c], bqa[c][kq], bqa[c][kq]);
            #pragma unroll
            for (int p = 0; p < NPAIR; ++p) {
                u64 ap = sa2[kk * SP + rt * NPAIR + p];
                #pragma unroll
                for (int c = 0; c < NCOL; ++c) FMA2A(acc[p * NCOL + c], ap, bp[c]);
            }
        }
    }
}

// ---------------- q projection + q-tilde: block = (64-batch tile, head) ----------------
// dyn smem: saf[2][2112] | sbt[2][3456] | qs[6144] | sts[64]  = 69376 B
__global__ void __launch_bounds__(256) k_qproj(const float* __restrict__ src,
                                               const float* __restrict__ src_ts,
                                               const float* __restrict__ freq,
                                               const float* __restrict__ phase,
                                               const float* __restrict__ Wq) {
    extern __shared__ __align__(16) float dynq[];
    float* saf[2] = { dynq, dynq + 2112 };
    float* sbt[2] = { dynq + 4224, dynq + 4224 + 3456 };
    float* qs  = dynq + 4224 + 6912;
    float* sts = qs + 6144;
    const int tid = threadIdx.x, ct = tid & 31, rt = tid >> 5;
    const int bt = blockIdx.x >> 2, h = blockIdx.x & 3, b0 = bt * 64;

    if (tid < 64) sts[tid] = src_ts[b0 + tid];
    __syncthreads();

    float areg[8]; float4 breg[3];

    // ---- phase 1: qs(64x96) = [src | time](64x256) @ Wq_h^T, 8 K-tiles, double-buffered
    #define LOAD_P1(KT) do {                                                     \
        const int m_ = (KT) + ct;                                                \
        _Pragma("unroll")                                                        \
        for (int j = 0; j < 8; ++j) {                                            \
            int row = rt + 8 * j;                                                \
            if (m_ < 128) areg[j] = src[(size_t)(b0 + row) * 128 + m_];          \
            else { int d_ = m_ - 128;                                            \
                   areg[j] = cosf(sts[row] * freq[d_] + phase[d_]); }            \
        }                                                                        \
        const int mp_ = ((KT) < 128 ? (KT) : (KT) + 128);                        \
        _Pragma("unroll")                                                        \
        for (int j = 0; j < 3; ++j) {                                            \
            int qidx = tid + 256 * j, col = qidx >> 3, q = qidx & 7;             \
            breg[j] = *(const float4*)&Wq[(size_t)(h * 96 + col) * 384 + mp_ + q * 4]; \
        } } while (0)
    #define STORE_AB(BUF) do {                                                   \
        _Pragma("unroll")                                                        \
        for (int j = 0; j < 8; ++j) saf[BUF][ct * 66 + rt + 8 * j] = areg[j];    \
        _Pragma("unroll")                                                        \
        for (int j = 0; j < 3; ++j) {                                            \
            int qidx = tid + 256 * j, col = qidx >> 3, q = qidx & 7;             \
            *(float4*)&sbt[BUF][col * 36 + q * 4] = breg[j];                     \
        } } while (0)

    LOAD_P1(0); STORE_AB(0);
    __syncthreads();
    u64 acc[12] = {};
    for (int t = 0; t < 8; ++t) {
        const int cur = t & 1;
        if (t < 7) LOAD_P1((t + 1) * 32);
        gemm_tile<4, 3, 33>(acc, saf[cur], sbt[cur], ct, rt);
        if (t < 7) STORE_AB(cur ^ 1);
        __syncthreads();
    }
    #pragma unroll
    for (int p = 0; p < 4; ++p)
        #pragma unroll
        for (int c = 0; c < 3; ++c) {
            float lo, hi; UPK2(lo, hi, acc[p * 3 + c]);
            qs[(rt * 8 + 2 * p) * 96 + ct + 32 * c] = lo;
            qs[(rt * 8 + 2 * p + 1) * 96 + ct + 32 * c] = hi;
        }
    __syncthreads();

    // ---- phase 2: qt(64x384) = qs(64x96) @ WkT_h, 4 col passes x 3 K-tiles
    for (int cp = 0; cp < 4; ++cp) {
        const int c0 = cp * 96;
        u64 a2[12] = {};
        for (int t = 0; t < 3; ++t) {
            const int kt = t * 32;
            __syncthreads();
            #pragma unroll
            for (int j = 0; j < 8; ++j)
                saf[0][ct * 66 + rt + 8 * j] = qs[(rt + 8 * j) * 96 + kt + ct];
            #pragma unroll
            for (int j = 0; j < 3; ++j) {
                int qidx = tid + 256 * j, col = qidx >> 3, q = qidx & 7;
                *(float4*)&sbt[0][col * 36 + q * 4] =
                    *(const float4*)&g_WkT[(size_t)(h * 384 + c0 + col) * 96 + kt + q * 4];
            }
            __syncthreads();
            gemm_tile<4, 3, 33>(a2, saf[0], sbt[0], ct, rt);
        }
        #pragma unroll
        for (int p = 0; p < 4; ++p)
            #pragma unroll
            for (int c = 0; c < 3; ++c) {
                float lo, hi; UPK2(lo, hi, a2[p * 3 + c]);
                g_qt[(size_t)(b0 + rt * 8 + 2 * p) * 1536 + h * 384 + c0 + ct + 32 * c] = lo;
                g_qt[(size_t)(b0 + rt * 8 + 2 * p + 1) * 1536 + h * 384 + c0 + ct + 32 * c] = hi;
            }
    }
    #undef LOAD_P1
    #undef STORE_AB
}

// ---------------- attention core: one block per batch element ----------------
__global__ void __launch_bounds__(256) k_attn(const float* __restrict__ seq,
                                              const float* __restrict__ seq_e,
                                              const float* __restrict__ seq_ts,
                                              const unsigned int* __restrict__ mask,
                                              const float* __restrict__ freq,
                                              const float* __restrict__ phase,
                                              float* __restrict__ attn_out) {
    __shared__ float kin[NN * 384];
    __shared__ float qts[1536];
    __shared__ float sc[HH][NN];
    __shared__ float pp[HH][NN];
    const int b = blockIdx.x;
    const int tid = threadIdx.x;
    const int w = tid >> 5, lane = tid & 31;

    const float4* seq4   = (const float4*)seq;
    const float4* seq_e4 = (const float4*)seq_e;
    for (int idx = tid; idx < NN * 32; idx += 256) {
        int n = idx >> 5, q = idx & 31;
        float4 a = seq4  [((size_t)b * NN + n) * 32 + q];
        float4 e = seq_e4[((size_t)b * NN + n) * 32 + q];
        *(float4*)&kin[n * 384 + q * 4]       = a;
        *(float4*)&kin[n * 384 + 128 + q * 4] = e;
    }
    for (int idx = tid; idx < NN * 128; idx += 256) {
        int n = idx >> 7, d = idx & 127;
        kin[n * 384 + 256 + d] = cosf(seq_ts[b * NN + n] * freq[d] + phase[d]);
    }
    const float4* qt4 = (const float4*)(g_qt + (size_t)b * 1536);
    for (int idx = tid; idx < 384; idx += 256)
        *(float4*)&qts[idx * 4] = qt4[idx];
    __syncthreads();

    for (int p = w; p < HH * NN; p += 8) {
        int h = p / NN, n = p - h * NN;
        float partial = 0.f;
        #pragma unroll
        for (int t = 0; t < 12; ++t)
            partial = fmaf(qts[h * 384 + lane + 32 * t], kin[n * 384 + lane + 32 * t], partial);
        #pragma unroll
        for (int off = 16; off; off >>= 1)
            partial += __shfl_xor_sync(0xffffffffu, partial, off);
        if (lane == 0) {
            float s = partial * SCALE;
            if (mask[b * NN + n] != 0u) s = -1.0e10f;
            sc[h][n] = s;
        }
    }
    __syncthreads();

    if (w < HH) {
        float v = (lane < NN) ? sc[w][lane] : -3.0e38f;
        float mx = v;
        #pragma unroll
        for (int off = 16; off; off >>= 1)
            mx = fmaxf(mx, __shfl_xor_sync(0xffffffffu, mx, off));
        float e = (lane < NN) ? expf(v - mx) : 0.f;
        float s = e;
        #pragma unroll
        for (int off = 16; off; off >>= 1)
            s += __shfl_xor_sync(0xffffffffu, s, off);
        float prob = e / s;
        if (lane < NN) {
            pp[w][lane] = prob;
            attn_out[((size_t)w * BB + b) * NN + lane] = prob;
        }
    }
    __syncthreads();

    for (int idx = tid; idx < 1536; idx += 256) {
        int h = idx / 384, j = idx - h * 384;
        float s = 0.f;
        #pragma unroll
        for (int n = 0; n < NN; ++n)
            s = fmaf(pp[h][n], kin[n * 384 + j], s);
        g_c[(size_t)b * 1536 + idx] = s;
    }
}

// ---------------- Wv apply: block = (64-batch tile, head), double-buffered ----------------
__global__ void __launch_bounds__(256) k_vout(const float* __restrict__ Wv) {
    __shared__ __align__(16) float saf[2][32 * 66];
    __shared__ __align__(16) float sbt[2][96 * 36];
    const int tid = threadIdx.x, ct = tid & 31, rt = tid >> 5;
    const int bt = blockIdx.x >> 2, h = blockIdx.x & 3, b0 = bt * 64;

    float areg[8]; float4 breg[3];
    #define LOAD_V(KT) do {                                                          \
        _Pragma("unroll")                                                            \
        for (int j = 0; j < 8; ++j)                                                  \
            areg[j] = g_c[(size_t)(b0 + rt + 8 * j) * 1536 + h * 384 + (KT) + ct];   \
        _Pragma("unroll")                                                            \
        for (int j = 0; j < 3; ++j) {                                                \
            int qidx = tid + 256 * j, col = qidx >> 3, q = qidx & 7;                 \
            breg[j] = *(const float4*)&Wv[(size_t)(h * 96 + col) * 384 + (KT) + q * 4]; \
        } } while (0)
    #define STORE_V(BUF) do {                                                        \
        _Pragma("unroll")                                                            \
        for (int j = 0; j < 8; ++j) saf[BUF][ct * 66 + rt + 8 * j] = areg[j];        \
        _Pragma("unroll")                                                            \
        for (int j = 0; j < 3; ++j) {                                                \
            int qidx = tid + 256 * j, col = qidx >> 3, q = qidx & 7;                 \
            *(float4*)&sbt[BUF][col * 36 + q * 4] = breg[j];                         \
        } } while (0)

    LOAD_V(0); STORE_V(0);
    __syncthreads();
    u64 acc[12] = {};
    for (int t = 0; t < 12; ++t) {
        const int cur = t & 1;
        if (t < 11) LOAD_V((t + 1) * 32);
        gemm_tile<4, 3, 33>(acc, saf[cur], sbt[cur], ct, rt);
        if (t < 11) STORE_V(cur ^ 1);
        __syncthreads();
    }
    #pragma unroll
    for (int p = 0; p < 4; ++p)
        #pragma unroll
        for (int c = 0; c < 3; ++c) {
            float lo, hi; UPK2(lo, hi, acc[p * 3 + c]);
            g_ao[(size_t)(b0 + rt * 8 + 2 * p) * 384 + h * 96 + ct + 32 * c] = lo;
            g_ao[(size_t)(b0 + rt * 8 + 2 * p + 1) * 384 + h * 96 + ct + 32 * c] = hi;
        }
    #undef LOAD_V
    #undef STORE_V
}

// ---------------- fc + bias + residual -> g_pre: block = (64-batch tile, col quarter) ----------------
__global__ void __launch_bounds__(256) k_fc(const float* __restrict__ src,
                                            const float* __restrict__ src_ts,
                                            const float* __restrict__ freq,
                                            const float* __restrict__ phase,
                                            const float* __restrict__ fc_w,
                                            const float* __restrict__ fc_b) {
    __shared__ __align__(16) float saf[2][32 * 66];
    __shared__ __align__(16) float sbt[2][96 * 36];
    const int tid = threadIdx.x, ct = tid & 31, rt = tid >> 5;
    const int bt = blockIdx.x >> 2, cq = blockIdx.x & 3, b0 = bt * 64;
    const int c0 = cq * 96;

    float areg[8]; float4 breg[3];
    #define LOAD_F(KT) do {                                                          \
        _Pragma("unroll")                                                            \
        for (int j = 0; j < 8; ++j)                                                  \
            areg[j] = g_ao[(size_t)(b0 + rt + 8 * j) * 384 + (KT) + ct];             \
        _Pragma("unroll")                                                            \
        for (int j = 0; j < 3; ++j) {                                                \
            int qidx = tid + 256 * j, col = qidx >> 3, q = qidx & 7;                 \
            breg[j] = *(const float4*)&fc_w[(size_t)(c0 + col) * 384 + (KT) + q * 4]; \
        } } while (0)
    #define STORE_F(BUF) do {                                                        \
        _Pragma("unroll")                                                            \
        for (int j = 0; j < 8; ++j) saf[BUF][ct * 66 + rt + 8 * j] = areg[j];        \
        _Pragma("unroll")                                                            \
        for (int j = 0; j < 3; ++j) {                                                \
            int qidx = tid + 256 * j, col = qidx >> 3, q = qidx & 7;                 \
            *(float4*)&sbt[BUF][col * 36 + q * 4] = breg[j];                         \
        } } while (0)

    LOAD_F(0); STORE_F(0);
    __syncthreads();
    u64 acc[12] = {};
    for (int t = 0; t < 12; ++t) {
        const int cur = t & 1;
        if (t < 11) LOAD_F((t + 1) * 32);
        gemm_tile<4, 3, 33>(acc, saf[cur], sbt[cur], ct, rt);
        if (t < 11) STORE_F(cur ^ 1);
        __syncthreads();
    }
    #pragma unroll
    for (int p = 0; p < 4; ++p)
        #pragma unroll
        for (int c = 0; c < 3; ++c) {
            float lo, hi; UPK2(lo, hi, acc[p * 3 + c]);
            const int col = c0 + ct + 32 * c;
            const int r0 = b0 + rt * 8 + 2 * p, r1 = r0 + 1;
            float add0 = fc_b[col], add1 = add0;
            if (col < 128) {
                add0 += src[(size_t)r0 * 128 + col];
                add1 += src[(size_t)r1 * 128 + col];
            } else if (col >= 256) {
                int d = col - 256;
                add0 += cosf(src_ts[r0] * freq[d] + phase[d]);
                add1 += cosf(src_ts[r1] * freq[d] + phase[d]);
            }
            g_pre[(size_t)r0 * 384 + col] = lo + add0;
            g_pre[(size_t)r1 * 384 + col] = hi + add1;
        }
    #undef LOAD_F
    #undef STORE_F
}

// ---------------- fused LN + MLP: 32 rows/block ----------------
// dyn smem: xs[512*34] | hs[128*34] | sbt[128*36]  = 105472 B
__global__ void __launch_bounds__(256) k_mlpln(const float* __restrict__ src,
                                               const float* __restrict__ ln_g,
                                               const float* __restrict__ ln_b,
                                               const float* __restrict__ m1_w,
                                               const float* __restrict__ m1_b,
                                               const float* __restrict__ m2_w,
                                               const float* __restrict__ m2_b,
                                               float* __restrict__ y) {
    extern __shared__ __align__(16) float dynm[];
    float* xs  = dynm;               // 512 x 34 col-major
    float* hs  = xs + 512 * 34;      // 128 x 34 col-major
    float* sbt = hs + 128 * 34;      // 128 x 36 (B transposed)
    const int tid = threadIdx.x, ct = tid & 31, rt = tid >> 5;
    const int b0 = blockIdx.x * 32;

    // load pre rows transposed + src
    for (int idx = tid; idx < 32 * 384; idx += 256) {
        int r = idx / 384, c = idx - r * 384;
        xs[c * 34 + r] = g_pre[(size_t)(b0 + r) * 384 + c];
    }
    for (int idx = tid; idx < 32 * 128; idx += 256) {
        int r = idx >> 7, d = idx & 127;
        xs[(384 + d) * 34 + r] = src[(size_t)(b0 + r) * 128 + d];
    }
    __syncthreads();

    // LayerNorm in place on cols [0,384): warp rt handles rows rt*4..rt*4+3
    for (int rr = 0; rr < 4; ++rr) {
        int row = rt * 4 + rr;
        float s1 = 0.f, s2 = 0.f;
        #pragma unroll
        for (int t = 0; t < 12; ++t) {
            float v = xs[(ct + 32 * t) * 34 + row];
            s1 += v; s2 = fmaf(v, v, s2);
        }
        #pragma unroll
        for (int off = 16; off; off >>= 1) {
            s1 += __shfl_xor_sync(0xffffffffu, s1, off);
            s2 += __shfl_xor_sync(0xffffffffu, s2, off);
        }
        float mu = s1 * (1.f / 384.f);
        float var = s2 * (1.f / 384.f) - mu * mu;
        float inv = rsqrtf(var + 1e-5f);
        #pragma unroll
        for (int t = 0; t < 12; ++t) {
            int j = ct + 32 * t;
            float v = xs[j * 34 + row];
            xs[j * 34 + row] = (v - mu) * inv * ln_g[j] + ln_b[j];
        }
    }

    float mb1[4], mb2[4];
    #pragma unroll
    for (int c = 0; c < 4; ++c) { mb1[c] = m1_b[ct + 32 * c]; mb2[c] = m2_b[ct + 32 * c]; }

    // GEMM1: h(32x128) = relu(x(32x512) @ m1_w^T + b), 16 K-tiles
    u64 acc[8] = {};
    for (int t = 0; t < 16; ++t) {
        const int kt = t * 32;
        __syncthreads();
        #pragma unroll
        for (int j = 0; j < 4; ++j) {
            int qidx = tid + 256 * j, col = qidx >> 3, q = qidx & 7;
            *(float4*)&sbt[col * 36 + q * 4] =
                *(const float4*)&m1_w[(size_t)col * 512 + kt + q * 4];
        }
        __syncthreads();
        gemm_tile<2, 4, 17>(acc, xs + kt * 34, sbt, ct, rt);
    }
    __syncthreads();
    #pragma unroll
    for (int p = 0; p < 2; ++p)
        #pragma unroll
        for (int c = 0; c < 4; ++c) {
            float lo, hi; UPK2(lo, hi, acc[p * 4 + c]);
            int col = ct + 32 * c;
            hs[col * 34 + rt * 4 + 2 * p]     = fmaxf(lo + mb1[c], 0.f);
            hs[col * 34 + rt * 4 + 2 * p + 1] = fmaxf(hi + mb1[c], 0.f);
        }

    // GEMM2: y = h(32x128) @ m2_w^T + b, 4 K-tiles
    u64 a2[8] = {};
    for (int t = 0; t < 4; ++t) {
        const int kt = t * 32;
        __syncthreads();
        #pragma unroll
        for (int j = 0; j < 4; ++j) {
            int qidx = tid + 256 * j, col = qidx >> 3, q = qidx & 7;
            *(float4*)&sbt[col * 36 + q * 4] =
                *(const float4*)&m2_w[(size_t)col * 128 + kt + q * 4];
        }
        __syncthreads();
        gemm_tile<2, 4, 17>(a2, hs + kt * 34, sbt, ct, rt);
    }
    #pragma unroll
    for (int p = 0; p < 2; ++p)
        #pragma unroll
        for (int c = 0; c < 4; ++c) {
            float lo, hi; UPK2(lo, hi, a2[p * 4 + c]);
            int col = ct + 32 * c;
            y[(size_t)(b0 + rt * 4 + 2 * p) * 128 + col]     = lo + mb2[c];
            y[(size_t)(b0 + rt * 4 + 2 * p + 1) * 128 + col] = hi + mb2[c];
        }
}

// ---------------- launch ----------------
extern "C" void kernel_launch(void* const* d_in, const int* in_sizes, int n_in,
                              void* d_out, int out_size) {
    const float* src    = (const float*)d_in[0];
    const float* seq    = (const float*)d_in[1];
    const float* seq_e  = (const float*)d_in[2];
    const float* src_ts = (const float*)d_in[3];
    const float* seq_ts = (const float*)d_in[4];
    const unsigned int* mask = (const unsigned int*)d_in[5];
    const float* freq   = (const float*)d_in[6];
    const float* phase  = (const float*)d_in[7];
    const float* Wq     = (const float*)d_in[8];
    const float* Wk     = (const float*)d_in[9];
    const float* Wv     = (const float*)d_in[10];
    const float* fc_w   = (const float*)d_in[11];
    const float* fc_b   = (const float*)d_in[12];
    const float* ln_g   = (const float*)d_in[13];
    const float* ln_b   = (const float*)d_in[14];
    const float* m1_w   = (const float*)d_in[15];
    const float* m1_b   = (const float*)d_in[16];
    const float* m2_w   = (const float*)d_in[17];
    const float* m2_b   = (const float*)d_in[18];

    float* y_out = (float*)d_out;
    float* attn_out = y_out + (size_t)BB * DD;

    const int qproj_smem = (2112 * 2 + 3456 * 2 + 6144 + 64) * 4;   // 69376
    const int mlp_smem   = (512 * 34 + 128 * 34 + 128 * 36) * 4;    // 105472
    cudaFuncSetAttribute(k_qproj, cudaFuncAttributeMaxDynamicSharedMemorySize, qproj_smem);
    cudaFuncSetAttribute(k_mlpln, cudaFuncAttributeMaxDynamicSharedMemorySize, mlp_smem);

    k_prep  <<<576, 256>>>(Wk);
    k_qproj <<<1024, 256, qproj_smem>>>(src, src_ts, freq, phase, Wq);
    k_attn  <<<BB, 256>>>(seq, seq_e, seq_ts, mask, freq, phase, attn_out);
    k_vout  <<<1024, 256>>>(Wv);
    k_fc    <<<1024, 256>>>(src, src_ts, freq, phase, fc_w, fc_b);
    k_mlpln <<<512, 256, mlp_smem>>>(src, ln_g, ln_b, m1_w, m1_b, m2_w, m2_b, y_out);
}